// round 1
// baseline (speedup 1.0000x reference)
#include <cuda_runtime.h>
#include <math.h>

#define HIDD 128
#define NMAX 100352
#define EMAX 602112

// ---------------- scratch (device globals; no allocation allowed) ----------
__device__ int   g_cnt[NMAX];
__device__ int   g_incl[NMAX];
__device__ int   g_bsum[256];
__device__ int   g_boff[256];
__device__ int   g_rowptr[NMAX + 1];
__device__ int   g_wpos[NMAX];
__device__ int   g_csr[EMAX];
__device__ float g_mean[(size_t)NMAX * HIDD];
__device__ float g_h0[(size_t)NMAX * HIDD];
__device__ float g_bnsum[HIDD];
__device__ float g_bnss[HIDD];
__device__ float g_scale[HIDD];
__device__ float g_shift[HIDD];

// ---------------- f32x2 helpers (FFMA2 only reachable via PTX) -------------
__device__ __forceinline__ unsigned long long pk2(float x) {
    unsigned long long r;
    asm("mov.b64 %0, {%1, %1};" : "=l"(r) : "f"(x));
    return r;
}
__device__ __forceinline__ void fma2(unsigned long long& d, unsigned long long a,
                                     unsigned long long b) {
    asm("fma.rn.f32x2 %0, %1, %2, %0;" : "+l"(d) : "l"(a), "l"(b));
}
__device__ __forceinline__ float2 up2(unsigned long long v) {
    float2 f;
    asm("mov.b64 {%0, %1}, %2;" : "=f"(f.x), "=f"(f.y) : "l"(v));
    return f;
}

// ---------------- small kernels --------------------------------------------
__global__ void k_zero(int n) {
    int i = blockIdx.x * blockDim.x + threadIdx.x;
    if (i < n) g_cnt[i] = 0;
    if (i < HIDD) { g_bnsum[i] = 0.f; g_bnss[i] = 0.f; }
}

__global__ void k_hist(const int* __restrict__ dst, int E) {
    int e = blockIdx.x * blockDim.x + threadIdx.x;
    if (e < E) atomicAdd(&g_cnt[dst[e]], 1);
}

__global__ void k_scan1(int n) {
    __shared__ int s[1024];
    int t = threadIdx.x;
    int i = blockIdx.x * 1024 + t;
    int v = (i < n) ? g_cnt[i] : 0;
    s[t] = v;
    __syncthreads();
    for (int off = 1; off < 1024; off <<= 1) {
        int x = (t >= off) ? s[t - off] : 0;
        __syncthreads();
        s[t] += x;
        __syncthreads();
    }
    if (i < n) g_incl[i] = s[t];
    if (t == 1023) g_bsum[blockIdx.x] = s[1023];
}

__global__ void k_scan2(int nb) {
    if (threadIdx.x == 0) {
        int run = 0;
        for (int b = 0; b < nb; b++) { g_boff[b] = run; run += g_bsum[b]; }
    }
}

__global__ void k_scan3(int n, int E) {
    int i = blockIdx.x * blockDim.x + threadIdx.x;
    if (i < n) {
        int excl = g_incl[i] - g_cnt[i] + g_boff[i >> 10];
        g_rowptr[i] = excl;
        g_wpos[i] = excl;
        if (i == 0) g_rowptr[n] = E;
    }
}

__global__ void k_fill(const int* __restrict__ src, const int* __restrict__ dst, int E) {
    int e = blockIdx.x * blockDim.x + threadIdx.x;
    if (e < E) {
        int d = dst[e];
        int p = atomicAdd(&g_wpos[d], 1);
        g_csr[p] = src[e];
    }
}

// ---------------- aggregation: one warp per node ----------------------------
__global__ void k_agg(const float* __restrict__ feat, float* __restrict__ outm,
                      int n, int layer2) {
    int w = (blockIdx.x * blockDim.x + threadIdx.x) >> 5;
    int lane = threadIdx.x & 31;
    if (w >= n) return;
    int r0 = g_rowptr[w], r1 = g_rowptr[w + 1];
    const float4* f4 = (const float4*)feat;
    float4 a = make_float4(0.f, 0.f, 0.f, 0.f);
    for (int j = r0; j < r1; j++) {
        int s = g_csr[j];
        float4 v = f4[(size_t)s * 32 + lane];
        a.x += v.x; a.y += v.y; a.z += v.z; a.w += v.w;
    }
    int deg = r1 - r0;
    float inv = (deg > 0) ? 1.f / (float)deg : 0.f;
    float4 m = make_float4(a.x * inv, a.y * inv, a.z * inv, a.w * inv);
    if (layer2) {
        if (deg > 0) {
            float4 sc = *(const float4*)(g_scale + lane * 4);
            float4 sh = *(const float4*)(g_shift + lane * 4);
            m.x = m.x * sc.x + sh.x; m.y = m.y * sc.y + sh.y;
            m.z = m.z * sc.z + sh.z; m.w = m.w * sc.w + sh.w;
        } else {
            m = make_float4(0.f, 0.f, 0.f, 0.f);
        }
    }
    ((float4*)outm)[(size_t)w * 32 + lane] = m;
}

// ---------------- BN finalize ----------------------------------------------
__global__ void k_bnfin(const float* __restrict__ gamma, const float* __restrict__ beta,
                        int n) {
    int c = threadIdx.x;
    if (c < HIDD) {
        float mu = g_bnsum[c] / (float)n;
        float var = g_bnss[c] / (float)n - mu * mu;
        float sc = gamma[c] * rsqrtf(var + 1e-5f);
        g_scale[c] = sc;
        g_shift[c] = beta[c] - mu * sc;
    }
}

// ---------------- fused GEMM + epilogue ------------------------------------
// out = [mean | root] @ [Wl ; Wr] + b ; then L2-normalize per row.
// LAYER 1: h0 = relu(normed), write h0, accumulate BN sums.
// LAYER 2: embed = normed -> embout ; preds = embed[:, :64] @ fcW + fcb.
template <int LAYER>
__global__ __launch_bounds__(256, 2) void k_gemm(
    const float* __restrict__ meanbuf, const float* __restrict__ featbuf,
    const float* __restrict__ Wl, const float* __restrict__ Wr,
    const float* __restrict__ bias, const float* __restrict__ fcW,
    const float* __restrict__ fcb, float* __restrict__ h0out,
    float* __restrict__ embout, float* __restrict__ predout, int n) {
    __shared__ float As[32 * 132];  // [k][m], padded stride 132
    __shared__ float Bs[32 * 128];  // [k][c]
    __shared__ float bnS[HIDD];
    __shared__ float bnQ[HIDD];

    const int t = threadIdx.x;
    const int tx = t & 15;   // col block (8 cols)
    const int ty = t >> 4;   // row block (8 rows)
    const int mtile = blockIdx.x * 128;

    if (LAYER == 1 && t < HIDD) { bnS[t] = 0.f; bnQ[t] = 0.f; }

    unsigned long long acc[8][4];
#pragma unroll
    for (int i = 0; i < 8; i++)
#pragma unroll
        for (int j = 0; j < 4; j++) acc[i][j] = 0ULL;

    for (int kt = 0; kt < 8; kt++) {
        const int kc = kt * 32;
        __syncthreads();
        // ---- load A tile (transposed into As[k][m]) ----
#pragma unroll
        for (int it = 0; it < 4; it++) {
            int row = (t >> 3) + it * 32;
            int kq = t & 7;
            int k = kc + kq * 4;
            int m = mtile + row;
            float4 v = make_float4(0.f, 0.f, 0.f, 0.f);
            if (m < n) {
                if (k < HIDD) {
                    v = *(const float4*)(meanbuf + (size_t)m * HIDD + k);
                } else {
                    int kk = k - HIDD;
                    v = *(const float4*)(featbuf + (size_t)m * HIDD + kk);
                    if (LAYER == 2) {
                        float4 sc = *(const float4*)(g_scale + kk);
                        float4 sh = *(const float4*)(g_shift + kk);
                        v.x = v.x * sc.x + sh.x; v.y = v.y * sc.y + sh.y;
                        v.z = v.z * sc.z + sh.z; v.w = v.w * sc.w + sh.w;
                    }
                }
            }
            int kl = kq * 4;
            As[(kl + 0) * 132 + row] = v.x;
            As[(kl + 1) * 132 + row] = v.y;
            As[(kl + 2) * 132 + row] = v.z;
            As[(kl + 3) * 132 + row] = v.w;
        }
        // ---- load B tile ----
#pragma unroll
        for (int it = 0; it < 4; it++) {
            int kl = (t >> 5) + it * 8;
            int c4 = (t & 31) * 4;
            int k = kc + kl;
            const float* W = (k < HIDD) ? (Wl + (size_t)k * HIDD)
                                        : (Wr + (size_t)(k - HIDD) * HIDD);
            *(float4*)(Bs + kl * 128 + c4) = *(const float4*)(W + c4);
        }
        __syncthreads();
        // ---- compute ----
#pragma unroll 4
        for (int k = 0; k < 32; k++) {
            float4 A0 = *(const float4*)(As + k * 132 + ty * 8);
            float4 A1 = *(const float4*)(As + k * 132 + ty * 8 + 4);
            float av[8] = {A0.x, A0.y, A0.z, A0.w, A1.x, A1.y, A1.z, A1.w};
            const unsigned long long* bp =
                (const unsigned long long*)(Bs + k * 128 + tx * 8);
            unsigned long long bb[4] = {bp[0], bp[1], bp[2], bp[3]};
#pragma unroll
            for (int i = 0; i < 8; i++) {
                unsigned long long p = pk2(av[i]);
#pragma unroll
                for (int j = 0; j < 4; j++) fma2(acc[i][j], p, bb[j]);
            }
        }
    }

    // ---- epilogue ----
    float bcol[8];
    {
        float4 b0 = *(const float4*)(bias + tx * 8);
        float4 b1 = *(const float4*)(bias + tx * 8 + 4);
        bcol[0] = b0.x; bcol[1] = b0.y; bcol[2] = b0.z; bcol[3] = b0.w;
        bcol[4] = b1.x; bcol[5] = b1.y; bcol[6] = b1.z; bcol[7] = b1.w;
    }
    float fw[8];
    float fb0 = 0.f;
    if (LAYER == 2) {
        fb0 = fcb[0];
#pragma unroll
        for (int j = 0; j < 8; j++) fw[j] = (tx < 8) ? fcW[tx * 8 + j] : 0.f;
    }
    float colsum[8], colss[8];
#pragma unroll
    for (int j = 0; j < 8; j++) { colsum[j] = 0.f; colss[j] = 0.f; }

#pragma unroll
    for (int i = 0; i < 8; i++) {
        int m = mtile + ty * 8 + i;
        float o[8];
#pragma unroll
        for (int j = 0; j < 4; j++) {
            float2 f = up2(acc[i][j]);
            o[2 * j] = f.x + bcol[2 * j];
            o[2 * j + 1] = f.y + bcol[2 * j + 1];
        }
        float ss = 0.f;
#pragma unroll
        for (int j = 0; j < 8; j++) ss += o[j] * o[j];
        ss += __shfl_xor_sync(0xffffffffu, ss, 1);
        ss += __shfl_xor_sync(0xffffffffu, ss, 2);
        ss += __shfl_xor_sync(0xffffffffu, ss, 4);
        ss += __shfl_xor_sync(0xffffffffu, ss, 8);
        float inv = 1.0f / fmaxf(sqrtf(ss), 1e-12f);

        if (LAYER == 1) {
            float h[8];
#pragma unroll
            for (int j = 0; j < 8; j++) h[j] = fmaxf(o[j] * inv, 0.f);
            if (m < n) {
                float* p = h0out + (size_t)m * HIDD + tx * 8;
                *(float4*)p = make_float4(h[0], h[1], h[2], h[3]);
                *(float4*)(p + 4) = make_float4(h[4], h[5], h[6], h[7]);
#pragma unroll
                for (int j = 0; j < 8; j++) {
                    colsum[j] += h[j];
                    colss[j] += h[j] * h[j];
                }
            }
        } else {
            float e[8];
#pragma unroll
            for (int j = 0; j < 8; j++) e[j] = o[j] * inv;
            if (m < n) {
                float* p = embout + (size_t)m * HIDD + tx * 8;
                *(float4*)p = make_float4(e[0], e[1], e[2], e[3]);
                *(float4*)(p + 4) = make_float4(e[4], e[5], e[6], e[7]);
            }
            float pp = 0.f;
            if (tx < 8) {
#pragma unroll
                for (int j = 0; j < 8; j++) pp += e[j] * fw[j];
            }
            pp += __shfl_xor_sync(0xffffffffu, pp, 1);
            pp += __shfl_xor_sync(0xffffffffu, pp, 2);
            pp += __shfl_xor_sync(0xffffffffu, pp, 4);
            pp += __shfl_xor_sync(0xffffffffu, pp, 8);
            if (tx == 0 && m < n) predout[m] = pp + fb0;
        }
    }

    if (LAYER == 1) {
#pragma unroll
        for (int j = 0; j < 8; j++) {
            atomicAdd(&bnS[tx * 8 + j], colsum[j]);
            atomicAdd(&bnQ[tx * 8 + j], colss[j]);
        }
        __syncthreads();
        if (t < HIDD) {
            atomicAdd(&g_bnsum[t], bnS[t]);
            atomicAdd(&g_bnss[t], bnQ[t]);
        }
    }
}

// ---------------- launch ----------------------------------------------------
extern "C" void kernel_launch(void* const* d_in, const int* in_sizes, int n_in,
                              void* d_out, int out_size) {
    const float* x = (const float*)d_in[0];
    const int* ei = (const int*)d_in[1];
    const float* W1l = (const float*)d_in[2];
    const float* b1l = (const float*)d_in[3];
    const float* W1r = (const float*)d_in[4];
    const float* gamma = (const float*)d_in[5];
    const float* beta = (const float*)d_in[6];
    const float* W2l = (const float*)d_in[7];
    const float* b2l = (const float*)d_in[8];
    const float* W2r = (const float*)d_in[9];
    const float* fcW = (const float*)d_in[10];
    const float* fcb = (const float*)d_in[11];

    const int n = in_sizes[0] / HIDD;
    const int E = in_sizes[1] / 2;
    const int* src = ei;
    const int* dst = ei + E;

    float* preds = (float*)d_out;
    float* embed = (float*)d_out + n;

    float* gmean;  cudaGetSymbolAddress((void**)&gmean, g_mean);
    float* gh0;    cudaGetSymbolAddress((void**)&gh0, g_h0);

    const int nb = (n + 1023) / 1024;

    k_zero<<<(n + 255) / 256, 256>>>(n);
    k_hist<<<(E + 255) / 256, 256>>>(dst, E);
    k_scan1<<<nb, 1024>>>(n);
    k_scan2<<<1, 32>>>(nb);
    k_scan3<<<(n + 255) / 256, 256>>>(n, E);
    k_fill<<<(E + 255) / 256, 256>>>(src, dst, E);

    // layer 1
    k_agg<<<(n + 7) / 8, 256>>>(x, gmean, n, 0);
    k_gemm<1><<<(n + 127) / 128, 256>>>(gmean, x, W1l, W1r, b1l, nullptr, nullptr,
                                        gh0, nullptr, nullptr, n);
    k_bnfin<<<1, 128>>>(gamma, beta, n);

    // layer 2
    k_agg<<<(n + 7) / 8, 256>>>(gh0, gmean, n, 1);
    k_gemm<2><<<(n + 127) / 128, 256>>>(gmean, gh0, W2l, W2r, b2l, fcW, fcb,
                                        nullptr, embed, preds, n);
}

// round 2
// speedup vs baseline: 1.0700x; 1.0700x over previous
#include <cuda_runtime.h>
#include <math.h>

#define HIDD 128
#define NMAX 100352
#define EMAX 602112

// ---------------- scratch (device globals; no allocation allowed) ----------
__device__ int   g_cnt[NMAX];
__device__ int   g_incl[NMAX];
__device__ int   g_bsum[256];
__device__ int   g_boff[256];
__device__ int   g_rowptr[NMAX + 1];
__device__ int   g_wpos[NMAX];
__device__ int   g_csr[EMAX];
__device__ float g_mean[(size_t)NMAX * HIDD];
__device__ float g_h0[(size_t)NMAX * HIDD];
__device__ float g_bnsum[HIDD];
__device__ float g_bnss[HIDD];
__device__ float g_scale[HIDD];
__device__ float g_shift[HIDD];

// ---------------- f32x2 helpers (FFMA2 only reachable via PTX) -------------
__device__ __forceinline__ unsigned long long pk2(float x) {
    unsigned long long r;
    asm("mov.b64 %0, {%1, %1};" : "=l"(r) : "f"(x));
    return r;
}
__device__ __forceinline__ void fma2(unsigned long long& d, unsigned long long a,
                                     unsigned long long b) {
    asm("fma.rn.f32x2 %0, %1, %2, %0;" : "+l"(d) : "l"(a), "l"(b));
}
__device__ __forceinline__ float2 up2(unsigned long long v) {
    float2 f;
    asm("mov.b64 {%0, %1}, %2;" : "=f"(f.x), "=f"(f.y) : "l"(v));
    return f;
}

// ---------------- small kernels --------------------------------------------
__global__ void k_zero(int n) {
    int i = blockIdx.x * blockDim.x + threadIdx.x;
    if (i < n) g_cnt[i] = 0;
    if (i < HIDD) { g_bnsum[i] = 0.f; g_bnss[i] = 0.f; }
}

__global__ void k_hist(const int* __restrict__ dst, int E) {
    int e = blockIdx.x * blockDim.x + threadIdx.x;
    if (e < E) atomicAdd(&g_cnt[dst[e]], 1);
}

__global__ void k_scan1(int n) {
    __shared__ int s[1024];
    int t = threadIdx.x;
    int i = blockIdx.x * 1024 + t;
    int v = (i < n) ? g_cnt[i] : 0;
    s[t] = v;
    __syncthreads();
    for (int off = 1; off < 1024; off <<= 1) {
        int x = (t >= off) ? s[t - off] : 0;
        __syncthreads();
        s[t] += x;
        __syncthreads();
    }
    if (i < n) g_incl[i] = s[t];
    if (t == 1023) g_bsum[blockIdx.x] = s[1023];
}

// parallel exclusive scan of block sums (nb <= 128)
__global__ void k_scan2(int nb) {
    __shared__ int s[128];
    int t = threadIdx.x;
    int v = (t < nb) ? g_bsum[t] : 0;
    s[t] = v;
    __syncthreads();
    for (int off = 1; off < 128; off <<= 1) {
        int x = (t >= off) ? s[t - off] : 0;
        __syncthreads();
        s[t] += x;
        __syncthreads();
    }
    if (t < nb) g_boff[t] = s[t] - v;
}

__global__ void k_scan3(int n, int E) {
    int i = blockIdx.x * blockDim.x + threadIdx.x;
    if (i < n) {
        int excl = g_incl[i] - g_cnt[i] + g_boff[i >> 10];
        g_rowptr[i] = excl;
        g_wpos[i] = excl;
        if (i == 0) g_rowptr[n] = E;
    }
}

__global__ void k_fill(const int* __restrict__ src, const int* __restrict__ dst, int E) {
    int e = blockIdx.x * blockDim.x + threadIdx.x;
    if (e < E) {
        int d = dst[e];
        int p = atomicAdd(&g_wpos[d], 1);
        g_csr[p] = src[e];
    }
}

// ---------------- aggregation: one warp per node ----------------------------
__global__ void k_agg(const float* __restrict__ feat, float* __restrict__ outm,
                      int n, int layer2) {
    int w = (blockIdx.x * blockDim.x + threadIdx.x) >> 5;
    int lane = threadIdx.x & 31;
    if (w >= n) return;
    int r0 = g_rowptr[w], r1 = g_rowptr[w + 1];
    const float4* f4 = (const float4*)feat;
    float4 a = make_float4(0.f, 0.f, 0.f, 0.f);
    int j = r0;
    for (; j + 1 < r1; j += 2) {
        int s0 = g_csr[j];
        int s1 = g_csr[j + 1];
        float4 v0 = f4[(size_t)s0 * 32 + lane];
        float4 v1 = f4[(size_t)s1 * 32 + lane];
        a.x += v0.x; a.y += v0.y; a.z += v0.z; a.w += v0.w;
        a.x += v1.x; a.y += v1.y; a.z += v1.z; a.w += v1.w;
    }
    if (j < r1) {
        int s0 = g_csr[j];
        float4 v0 = f4[(size_t)s0 * 32 + lane];
        a.x += v0.x; a.y += v0.y; a.z += v0.z; a.w += v0.w;
    }
    int deg = r1 - r0;
    float inv = (deg > 0) ? 1.f / (float)deg : 0.f;
    float4 m = make_float4(a.x * inv, a.y * inv, a.z * inv, a.w * inv);
    if (layer2) {
        if (deg > 0) {
            float4 sc = *(const float4*)(g_scale + lane * 4);
            float4 sh = *(const float4*)(g_shift + lane * 4);
            m.x = m.x * sc.x + sh.x; m.y = m.y * sc.y + sh.y;
            m.z = m.z * sc.z + sh.z; m.w = m.w * sc.w + sh.w;
        } else {
            m = make_float4(0.f, 0.f, 0.f, 0.f);
        }
    }
    ((float4*)outm)[(size_t)w * 32 + lane] = m;
}

// ---------------- BN finalize ----------------------------------------------
__global__ void k_bnfin(const float* __restrict__ gamma, const float* __restrict__ beta,
                        int n) {
    int c = threadIdx.x;
    if (c < HIDD) {
        float mu = g_bnsum[c] / (float)n;
        float var = g_bnss[c] / (float)n - mu * mu;
        float sc = gamma[c] * rsqrtf(var + 1e-5f);
        g_scale[c] = sc;
        g_shift[c] = beta[c] - mu * sc;
    }
}

// ---------------- fused GEMM + epilogue ------------------------------------
// out = [mean | root] @ [Wl ; Wr] + b ; then L2-normalize per row.
// Thread (tx,ty) owns rows mtile+ty*8..+7, columns tx+16*q for q=0..7.
// B smem stores column PAIRS (c, c+16) adjacently so the compute-phase read
// is a conflict-free LDS.64: Bs[k*128 + jj*32 + tx*2] holds cols
// (tx+32jj, tx+16+32jj) = (tx+16*(2jj), tx+16*(2jj+1)).
// LAYER 1: h0 = relu(normed), write h0, accumulate BN sums.
// LAYER 2: embed = normed -> embout ; preds = embed[:, :64] @ fcW + fcb.
template <int LAYER>
__global__ __launch_bounds__(256, 2) void k_gemm(
    const float* __restrict__ meanbuf, const float* __restrict__ featbuf,
    const float* __restrict__ Wl, const float* __restrict__ Wr,
    const float* __restrict__ bias, const float* __restrict__ fcW,
    const float* __restrict__ fcb, float* __restrict__ h0out,
    float* __restrict__ embout, float* __restrict__ predout, int n) {
    __shared__ float As[32 * 132];  // [k][m], padded stride 132
    __shared__ float Bs[32 * 128];  // [k][pair-interleaved cols]
    __shared__ float bnS[HIDD];
    __shared__ float bnQ[HIDD];

    const int t = threadIdx.x;
    const int tx = t & 15;   // 16 col lanes
    const int ty = t >> 4;   // 16 row groups
    const int mtile = blockIdx.x * 128;

    if (LAYER == 1 && t < HIDD) { bnS[t] = 0.f; bnQ[t] = 0.f; }

    unsigned long long acc[8][4];
#pragma unroll
    for (int i = 0; i < 8; i++)
#pragma unroll
        for (int j = 0; j < 4; j++) acc[i][j] = 0ULL;

    for (int kt = 0; kt < 8; kt++) {
        const int kc = kt * 32;
        __syncthreads();
        // ---- load A tile (transposed into As[k][m]) ----
#pragma unroll
        for (int it = 0; it < 4; it++) {
            int row = (t >> 3) + it * 32;
            int kq = t & 7;
            int k = kc + kq * 4;
            int m = mtile + row;
            float4 v = make_float4(0.f, 0.f, 0.f, 0.f);
            if (m < n) {
                if (k < HIDD) {
                    v = *(const float4*)(meanbuf + (size_t)m * HIDD + k);
                } else {
                    int kk = k - HIDD;
                    v = *(const float4*)(featbuf + (size_t)m * HIDD + kk);
                    if (LAYER == 2) {
                        float4 sc = *(const float4*)(g_scale + kk);
                        float4 sh = *(const float4*)(g_shift + kk);
                        v.x = v.x * sc.x + sh.x; v.y = v.y * sc.y + sh.y;
                        v.z = v.z * sc.z + sh.z; v.w = v.w * sc.w + sh.w;
                    }
                }
            }
            int kl = kq * 4;
            As[(kl + 0) * 132 + row] = v.x;
            As[(kl + 1) * 132 + row] = v.y;
            As[(kl + 2) * 132 + row] = v.z;
            As[(kl + 3) * 132 + row] = v.w;
        }
        // ---- load B tile (scatter into pair-interleaved layout) ----
#pragma unroll
        for (int it = 0; it < 4; it++) {
            int kl = (t >> 5) + it * 8;
            int c4 = (t & 31) * 4;
            int k = kc + kl;
            const float* W = (k < HIDD) ? (Wl + (size_t)k * HIDD)
                                        : (Wr + (size_t)(k - HIDD) * HIDD);
            float4 w = *(const float4*)(W + c4);
            float vv[4] = {w.x, w.y, w.z, w.w};
#pragma unroll
            for (int e = 0; e < 4; e++) {
                int c = c4 + e;
                int off = ((c >> 5) << 5) + ((c & 15) << 1) + ((c >> 4) & 1);
                Bs[kl * 128 + off] = vv[e];
            }
        }
        __syncthreads();
        // ---- compute ----
#pragma unroll 8
        for (int k = 0; k < 32; k++) {
            float4 A0 = *(const float4*)(As + k * 132 + ty * 8);
            float4 A1 = *(const float4*)(As + k * 132 + ty * 8 + 4);
            float av[8] = {A0.x, A0.y, A0.z, A0.w, A1.x, A1.y, A1.z, A1.w};
            const unsigned long long* bp =
                (const unsigned long long*)(Bs + k * 128 + tx * 2);
            unsigned long long bb[4] = {bp[0], bp[16], bp[32], bp[48]};
#pragma unroll
            for (int i = 0; i < 8; i++) {
                unsigned long long p = pk2(av[i]);
#pragma unroll
                for (int j = 0; j < 4; j++) fma2(acc[i][j], p, bb[j]);
            }
        }
    }

    // ---- epilogue (column q -> global col tx + 16*q) ----
    float bcol[8];
#pragma unroll
    for (int q = 0; q < 8; q++) bcol[q] = bias[tx + 16 * q];

    float fw[4];
    float fb0 = 0.f;
    if (LAYER == 2) {
        fb0 = fcb[0];
#pragma unroll
        for (int q = 0; q < 4; q++) fw[q] = fcW[tx + 16 * q];  // cols 0..63
    }
    float colsum[8], colss[8];
#pragma unroll
    for (int q = 0; q < 8; q++) { colsum[q] = 0.f; colss[q] = 0.f; }

#pragma unroll
    for (int i = 0; i < 8; i++) {
        int m = mtile + ty * 8 + i;
        float o[8];
#pragma unroll
        for (int j = 0; j < 4; j++) {
            float2 f = up2(acc[i][j]);
            o[2 * j] = f.x + bcol[2 * j];
            o[2 * j + 1] = f.y + bcol[2 * j + 1];
        }
        float ss = 0.f;
#pragma unroll
        for (int q = 0; q < 8; q++) ss += o[q] * o[q];
        ss += __shfl_xor_sync(0xffffffffu, ss, 1);
        ss += __shfl_xor_sync(0xffffffffu, ss, 2);
        ss += __shfl_xor_sync(0xffffffffu, ss, 4);
        ss += __shfl_xor_sync(0xffffffffu, ss, 8);
        float inv = 1.0f / fmaxf(sqrtf(ss), 1e-12f);

        if (LAYER == 1) {
            float h[8];
#pragma unroll
            for (int q = 0; q < 8; q++) h[q] = fmaxf(o[q] * inv, 0.f);
            if (m < n) {
                float* p = h0out + (size_t)m * HIDD + tx;
#pragma unroll
                for (int q = 0; q < 8; q++) p[16 * q] = h[q];
#pragma unroll
                for (int q = 0; q < 8; q++) {
                    colsum[q] += h[q];
                    colss[q] += h[q] * h[q];
                }
            }
        } else {
            float e[8];
#pragma unroll
            for (int q = 0; q < 8; q++) e[q] = o[q] * inv;
            if (m < n) {
                float* p = embout + (size_t)m * HIDD + tx;
#pragma unroll
                for (int q = 0; q < 8; q++) p[16 * q] = e[q];
            }
            float pp = 0.f;
#pragma unroll
            for (int q = 0; q < 4; q++) pp += e[q] * fw[q];
            pp += __shfl_xor_sync(0xffffffffu, pp, 1);
            pp += __shfl_xor_sync(0xffffffffu, pp, 2);
            pp += __shfl_xor_sync(0xffffffffu, pp, 4);
            pp += __shfl_xor_sync(0xffffffffu, pp, 8);
            if (tx == 0 && m < n) predout[m] = pp + fb0;
        }
    }

    if (LAYER == 1) {
#pragma unroll
        for (int q = 0; q < 8; q++) {
            atomicAdd(&bnS[tx + 16 * q], colsum[q]);
            atomicAdd(&bnQ[tx + 16 * q], colss[q]);
        }
        __syncthreads();
        if (t < HIDD) {
            atomicAdd(&g_bnsum[t], bnS[t]);
            atomicAdd(&g_bnss[t], bnQ[t]);
        }
    }
}

// ---------------- launch ----------------------------------------------------
extern "C" void kernel_launch(void* const* d_in, const int* in_sizes, int n_in,
                              void* d_out, int out_size) {
    const float* x = (const float*)d_in[0];
    const int* ei = (const int*)d_in[1];
    const float* W1l = (const float*)d_in[2];
    const float* b1l = (const float*)d_in[3];
    const float* W1r = (const float*)d_in[4];
    const float* gamma = (const float*)d_in[5];
    const float* beta = (const float*)d_in[6];
    const float* W2l = (const float*)d_in[7];
    const float* b2l = (const float*)d_in[8];
    const float* W2r = (const float*)d_in[9];
    const float* fcW = (const float*)d_in[10];
    const float* fcb = (const float*)d_in[11];

    const int n = in_sizes[0] / HIDD;
    const int E = in_sizes[1] / 2;
    const int* src = ei;
    const int* dst = ei + E;

    float* preds = (float*)d_out;
    float* embed = (float*)d_out + n;

    float* gmean;  cudaGetSymbolAddress((void**)&gmean, g_mean);
    float* gh0;    cudaGetSymbolAddress((void**)&gh0, g_h0);

    const int nb = (n + 1023) / 1024;

    k_zero<<<(n + 255) / 256, 256>>>(n);
    k_hist<<<(E + 255) / 256, 256>>>(dst, E);
    k_scan1<<<nb, 1024>>>(n);
    k_scan2<<<1, 128>>>(nb);
    k_scan3<<<(n + 255) / 256, 256>>>(n, E);
    k_fill<<<(E + 255) / 256, 256>>>(src, dst, E);

    // layer 1
    k_agg<<<(n + 7) / 8, 256>>>(x, gmean, n, 0);
    k_gemm<1><<<(n + 127) / 128, 256>>>(gmean, x, W1l, W1r, b1l, nullptr, nullptr,
                                        gh0, nullptr, nullptr, n);
    k_bnfin<<<1, 128>>>(gamma, beta, n);

    // layer 2
    k_agg<<<(n + 7) / 8, 256>>>(gh0, gmean, n, 1);
    k_gemm<2><<<(n + 127) / 128, 256>>>(gmean, gh0, W2l, W2r, b2l, fcW, fcb,
                                        nullptr, embed, preds, n);
}